// round 2
// baseline (speedup 1.0000x reference)
#include <cuda_runtime.h>
#include <math.h>

#define BB 64
#define NN 512
#define DD 128
#define KT 16

typedef unsigned long long ull;

__device__ __forceinline__ ull pack2(float lo, float hi){
    ull r; asm("mov.b64 %0, {%1, %2};" : "=l"(r) : "f"(lo), "f"(hi)); return r;
}
__device__ __forceinline__ float2 unpack2(ull v){
    float2 f; asm("mov.b64 {%0, %1}, %2;" : "=f"(f.x), "=f"(f.y) : "l"(v)); return f;
}
__device__ __forceinline__ void fma2(ull &d, ull a, ull b){
    asm("fma.rn.f32x2 %0, %1, %2, %0;" : "+l"(d) : "l"(a), "l"(b));
}
__device__ __forceinline__ unsigned sm32(const void* p){
    return (unsigned)__cvta_generic_to_shared(p);
}
__device__ __forceinline__ void cp16(unsigned dst, const void* src){
    asm volatile("cp.async.cg.shared.global [%0], [%1], 16;" :: "r"(dst), "l"(src));
}
__device__ __forceinline__ void cp_commit(){ asm volatile("cp.async.commit_group;"); }
__device__ __forceinline__ void cp_wait0(){ asm volatile("cp.async.wait_group 0;" ::: "memory"); }

// Scratch (static device globals; no allocation)
__device__ float g_ET[BB*DD*NN];          // E transposed per batch: [b][d][i]
__device__ float g_z [BB*NN*DD];          // z = E @ W
__device__ float g_P [(size_t)BB*NN*NN];  // masked exp weights
__device__ float g_el[BB*NN];
__device__ float g_er[BB*NN];
__device__ float g_th[BB];
__device__ float g_cs[BB*4*NN];           // partial colsums per i-tile
__device__ float g_pool[BB*4*DD];         // partial pooled sums per j-tile

// 32 FFMA2 block: A0..A3 = dup'd a-pairs (rows), B0,B1 = natural b-pairs (cols)
#define FMA_BLOCK \
    fma2(acc[0][0],A0.x,B0.x); fma2(acc[0][1],A0.x,B0.y); fma2(acc[0][2],A0.x,B1.x); fma2(acc[0][3],A0.x,B1.y); \
    fma2(acc[1][0],A0.y,B0.x); fma2(acc[1][1],A0.y,B0.y); fma2(acc[1][2],A0.y,B1.x); fma2(acc[1][3],A0.y,B1.y); \
    fma2(acc[2][0],A1.x,B0.x); fma2(acc[2][1],A1.x,B0.y); fma2(acc[2][2],A1.x,B1.x); fma2(acc[2][3],A1.x,B1.y); \
    fma2(acc[3][0],A1.y,B0.x); fma2(acc[3][1],A1.y,B0.y); fma2(acc[3][2],A1.y,B1.x); fma2(acc[3][3],A1.y,B1.y); \
    fma2(acc[4][0],A2.x,B0.x); fma2(acc[4][1],A2.x,B0.y); fma2(acc[4][2],A2.x,B1.x); fma2(acc[4][3],A2.x,B1.y); \
    fma2(acc[5][0],A2.y,B0.x); fma2(acc[5][1],A2.y,B0.y); fma2(acc[5][2],A2.y,B1.x); fma2(acc[5][3],A2.y,B1.y); \
    fma2(acc[6][0],A3.x,B0.x); fma2(acc[6][1],A3.x,B0.y); fma2(acc[6][2],A3.x,B1.x); fma2(acc[6][3],A3.x,B1.y); \
    fma2(acc[7][0],A3.y,B0.x); fma2(acc[7][1],A3.y,B0.y); fma2(acc[7][2],A3.y,B1.x); fma2(acc[7][3],A3.y,B1.y);

// Prefetch B chunk k0 into Bs[buf] via cp.async (2 x 16B per thread)
#define CPB(bufidx, k0v, Bbase, ldb) do { \
    int _k0 = (k0v); \
    _Pragma("unroll") \
    for (int _p = 0; _p < 2; _p++){ \
        int _f = tid + 256*_p; int _kk = _f >> 5; int _cc = (_f & 31) * 4; \
        cp16(sm32(&Bs[bufidx][_kk][_cc]), (Bbase) + (size_t)(_k0+_kk)*(ldb) + _cc); \
    } \
    cp_commit(); \
} while(0)

// LDG A chunk k0 into areg (stride-32 scalar loads, coalesced)
#define LDA(k0v, Abase, lda) do { \
    int _k0 = (k0v); \
    _Pragma("unroll") \
    for (int _r = 0; _r < 2; _r++) \
        _Pragma("unroll") \
        for (int _q = 0; _q < 4; _q++) \
            areg[_r*4+_q] = (Abase)[(size_t)(_k0 + 2*w + _r)*(lda) + lane + 32*_q]; \
} while(0)

// Store areg duplicated into As2[buf] (STS.64, 2-way conflict)
#define STA(bufidx) do { \
    _Pragma("unroll") \
    for (int _r = 0; _r < 2; _r++) \
        _Pragma("unroll") \
        for (int _q = 0; _q < 4; _q++) \
            *(ull*)&As2[bufidx][2*w+_r][2*(lane+32*_q)] = pack2(areg[_r*4+_q], areg[_r*4+_q]); \
} while(0)

#define GEMM_MAIN(NC, Abase, lda, Bbase, ldb) \
    float areg[8]; \
    CPB(0, 0, Bbase, ldb); \
    LDA(0, Abase, lda); \
    STA(0); \
    cp_wait0(); \
    __syncthreads(); \
    _Pragma("unroll 1") \
    for (int c = 0; c < (NC); c++){ \
        int buf = c & 1; \
        if (c + 1 < (NC)){ \
            CPB(buf^1, (c+1)*KT, Bbase, ldb); \
            LDA((c+1)*KT, Abase, lda); \
        } \
        _Pragma("unroll") \
        for (int k = 0; k < KT; k++){ \
            ulonglong2 A0 = *(const ulonglong2*)&As2[buf][k][8*ty]; \
            ulonglong2 A1 = *(const ulonglong2*)&As2[buf][k][8*ty+4]; \
            ulonglong2 A2 = *(const ulonglong2*)&As2[buf][k][128+8*ty]; \
            ulonglong2 A3 = *(const ulonglong2*)&As2[buf][k][128+8*ty+4]; \
            ulonglong2 B0 = *(const ulonglong2*)&Bs[buf][k][4*tx]; \
            ulonglong2 B1 = *(const ulonglong2*)&Bs[buf][k][64+4*tx]; \
            FMA_BLOCK \
        } \
        if (c + 1 < (NC)){ \
            STA(buf^1); \
            cp_wait0(); \
            __syncthreads(); \
        } \
    }

// ---------------- transpose: g_ET[b][d][i] = E[b][i][d] ----------------
__global__ void k_T(const float* __restrict__ E){
    __shared__ float t[32][33];
    int b  = blockIdx.z;
    int i0 = blockIdx.x * 32;
    int d0 = blockIdx.y * 32;
    int tx = threadIdx.x, ty = threadIdx.y;   // (32, 8)
    const float* Eb = E + (size_t)b*NN*DD;
    #pragma unroll
    for (int yy = 0; yy < 32; yy += 8)
        t[ty+yy][tx] = Eb[(size_t)(i0+ty+yy)*DD + d0 + tx];
    __syncthreads();
    float* ETb = g_ET + (size_t)b*DD*NN;
    #pragma unroll
    for (int yy = 0; yy < 32; yy += 8)
        ETb[(size_t)(d0+ty+yy)*NN + i0 + tx] = t[tx][ty+yy];
}

// ---------------- thresh[b] = ||sum_i e_i||^2 / N^2 ----------------
__global__ void k_thresh(const float* __restrict__ E){
    int b = blockIdx.x; int t = threadIdx.x;  // 128 threads
    const float* Eb = E + (size_t)b*NN*DD;
    float s = 0.f;
    for (int i = 0; i < NN; i++) s += Eb[(size_t)i*DD + t];
    __shared__ float red[DD];
    red[t] = s * s;
    __syncthreads();
    for (int o = 64; o > 0; o >>= 1){
        if (t < o) red[t] += red[t+o];
        __syncthreads();
    }
    if (t == 0) g_th[b] = red[0] * (1.f / ((float)NN * (float)NN));
}

// ---------------- z = E @ W  (+ fused el/er) ----------------
__global__ void __launch_bounds__(256,2) k_z(const float* __restrict__ W,
                                             const float* __restrict__ attn_l,
                                             const float* __restrict__ attn_r){
    __shared__ float As2[2][KT][256];
    __shared__ float Bs [2][KT][128];
    int it = blockIdx.x, b = blockIdx.y;
    int tid = threadIdx.x, tx = tid & 15, ty = tid >> 4;
    int w = tid >> 5, lane = tid & 31;
    const float* ETb = g_ET + (size_t)b*DD*NN;
    int i0 = it * 128;
    const float* Abase = ETb + i0;

    ull acc[8][4];
    #pragma unroll
    for (int r = 0; r < 8; r++)
        #pragma unroll
        for (int p = 0; p < 4; p++) acc[r][p] = 0ull;

    GEMM_MAIN(DD/KT, Abase, NN, W, DD)

    float al[8], ar[8];
    #pragma unroll
    for (int s = 0; s < 8; s++){
        int d = tx*4 + (s&3) + ((s>>2)<<6);
        al[s] = attn_l[d]; ar[s] = attn_r[d];
    }
    float elp[8], erp[8];
    float* zb = g_z + (size_t)b*NN*DD;
    #pragma unroll
    for (int r = 0; r < 8; r++){
        int i = i0 + ty*4 + (r&3) + ((r>>2)<<6);
        float v[8];
        #pragma unroll
        for (int p = 0; p < 4; p++){ float2 u = unpack2(acc[r][p]); v[p*2] = u.x; v[p*2+1] = u.y; }
        *(float4*)&zb[(size_t)i*DD + tx*4]      = make_float4(v[0],v[1],v[2],v[3]);
        *(float4*)&zb[(size_t)i*DD + 64 + tx*4] = make_float4(v[4],v[5],v[6],v[7]);
        float pe = 0.f, pr = 0.f;
        #pragma unroll
        for (int s = 0; s < 8; s++){ pe += v[s]*al[s]; pr += v[s]*ar[s]; }
        elp[r] = pe; erp[r] = pr;
    }
    __syncthreads();
    float* redl = &As2[0][0][0];
    float* redr = redl + 2048;
    #pragma unroll
    for (int r = 0; r < 8; r++){
        int il = ty*4 + (r&3) + ((r>>2)<<6);
        redl[tx*128 + il] = elp[r];
        redr[tx*128 + il] = erp[r];
    }
    __syncthreads();
    if (tid < 128){
        float se = 0.f, sr = 0.f;
        #pragma unroll
        for (int x = 0; x < 16; x++){ se += redl[x*128 + tid]; sr += redr[x*128 + tid]; }
        g_el[b*NN + i0 + tid] = se;
        g_er[b*NN + i0 + tid] = sr;
    }
}

// ---------------- scores -> P (masked exp), partial colsums ----------------
__global__ void __launch_bounds__(256,2) k_scores(){
    __shared__ float As2[2][KT][256];
    __shared__ float Bs [2][KT][128];
    int it = blockIdx.x, jt = blockIdx.y, b = blockIdx.z;
    int tid = threadIdx.x, tx = tid & 15, ty = tid >> 4;
    int w = tid >> 5, lane = tid & 31;
    const float* ETb = g_ET + (size_t)b*DD*NN;
    int i0 = it * 128, j0 = jt * 128;
    const float* Abase = ETb + i0;
    const float* Bbase = ETb + j0;

    ull acc[8][4];
    #pragma unroll
    for (int r = 0; r < 8; r++)
        #pragma unroll
        for (int p = 0; p < 4; p++) acc[r][p] = 0ull;

    GEMM_MAIN(DD/KT, Abase, NN, Bbase, NN)

    float th = g_th[b];
    int gi[8], gj[8]; float eli[8], erj[8];
    #pragma unroll
    for (int r = 0; r < 8; r++){ gi[r] = i0 + ty*4 + (r&3) + ((r>>2)<<6); eli[r] = g_el[b*NN + gi[r]]; }
    #pragma unroll
    for (int s = 0; s < 8; s++){ gj[s] = j0 + tx*4 + (s&3) + ((s>>2)<<6); erj[s] = g_er[b*NN + gj[s]]; }

    float cs[8];
    #pragma unroll
    for (int s = 0; s < 8; s++) cs[s] = 0.f;
    float* Pb = g_P + (size_t)b*NN*NN;
    #pragma unroll
    for (int r = 0; r < 8; r++){
        float v[8];
        #pragma unroll
        for (int p = 0; p < 4; p++){ float2 u = unpack2(acc[r][p]); v[p*2] = u.x; v[p*2+1] = u.y; }
        float pv[8];
        #pragma unroll
        for (int s = 0; s < 8; s++){
            float e = eli[r] + erj[s];
            e = e > 0.f ? e : 0.2f * e;
            float p = (v[s] > th || gi[r] == gj[s]) ? expf(e) : 0.f;
            pv[s] = p; cs[s] += p;
        }
        *(float4*)&Pb[(size_t)gi[r]*NN + j0 + tx*4]      = make_float4(pv[0],pv[1],pv[2],pv[3]);
        *(float4*)&Pb[(size_t)gi[r]*NN + j0 + 64 + tx*4] = make_float4(pv[4],pv[5],pv[6],pv[7]);
    }
    __syncthreads();
    float* red = &As2[0][0][0];
    #pragma unroll
    for (int s = 0; s < 8; s++) red[ty*128 + (gj[s]-j0)] = cs[s];
    __syncthreads();
    if (tid < 128){
        float t = 0.f;
        #pragma unroll
        for (int x = 0; x < 16; x++) t += red[x*128 + tid];
        g_cs[(b*4 + it)*NN + j0 + tid] = t;
    }
}

// ---------------- h = P^T z / colsum; elu(+bias); partial pool ----------------
__global__ void __launch_bounds__(256,2) k_pv(const float* __restrict__ bias){
    __shared__ float As2[2][KT][256];
    __shared__ float Bs [2][KT][128];
    int jt = blockIdx.x, b = blockIdx.y;
    int tid = threadIdx.x, tx = tid & 15, ty = tid >> 4;
    int w = tid >> 5, lane = tid & 31;
    const float* Pb = g_P + (size_t)b*NN*NN;
    const float* zb = g_z + (size_t)b*NN*DD;
    int j0 = jt * 128;
    const float* Abase = Pb + j0;   // A[k=i][m=j]

    ull acc[8][4];
    #pragma unroll
    for (int r = 0; r < 8; r++)
        #pragma unroll
        for (int p = 0; p < 4; p++) acc[r][p] = 0ull;

    GEMM_MAIN(NN/KT, Abase, NN, zb, DD)

    float inv[8];
    #pragma unroll
    for (int r = 0; r < 8; r++){
        int j = j0 + ty*4 + (r&3) + ((r>>2)<<6);
        float c0 = g_cs[(b*4 + 0)*NN + j] + g_cs[(b*4 + 1)*NN + j]
                 + g_cs[(b*4 + 2)*NN + j] + g_cs[(b*4 + 3)*NN + j];
        inv[r] = 1.f / c0;
    }
    float bi[8]; int dl[8];
    #pragma unroll
    for (int s = 0; s < 8; s++){ dl[s] = tx*4 + (s&3) + ((s>>2)<<6); bi[s] = bias[dl[s]]; }

    float pd[8];
    #pragma unroll
    for (int s = 0; s < 8; s++) pd[s] = 0.f;
    #pragma unroll
    for (int r = 0; r < 8; r++){
        float v[8];
        #pragma unroll
        for (int p = 0; p < 4; p++){ float2 u = unpack2(acc[r][p]); v[p*2] = u.x; v[p*2+1] = u.y; }
        #pragma unroll
        for (int s = 0; s < 8; s++){
            float h = v[s]*inv[r] + bi[s];
            h = h > 0.f ? h : expm1f(h);
            pd[s] += h;
        }
    }
    __syncthreads();
    float* red = &As2[0][0][0];
    #pragma unroll
    for (int s = 0; s < 8; s++) red[ty*128 + dl[s]] = pd[s];
    __syncthreads();
    if (tid < 128){
        float t = 0.f;
        #pragma unroll
        for (int x = 0; x < 16; x++) t += red[x*128 + tid];
        g_pool[(b*4 + jt)*DD + tid] = t;
    }
}

// ---------------- final: mean over nodes ----------------
__global__ void k_out(float* __restrict__ out){
    int b = blockIdx.x, d = threadIdx.x;
    float s = g_pool[(b*4+0)*DD + d] + g_pool[(b*4+1)*DD + d]
            + g_pool[(b*4+2)*DD + d] + g_pool[(b*4+3)*DD + d];
    out[b*DD + d] = s * (1.f / (float)NN);
}

extern "C" void kernel_launch(void* const* d_in, const int* in_sizes, int n_in,
                              void* d_out, int out_size){
    const float* E    = (const float*)d_in[0];
    const float* W    = (const float*)d_in[1];
    const float* al   = (const float*)d_in[2];
    const float* ar   = (const float*)d_in[3];
    const float* bias = (const float*)d_in[4];
    float* out = (float*)d_out;

    k_T     <<<dim3(16,4,64), dim3(32,8)>>>(E);
    k_thresh<<<64, 128>>>(E);
    k_z     <<<dim3(4,64),   256>>>(W, al, ar);
    k_scores<<<dim3(4,4,64), 256>>>();
    k_pv    <<<dim3(4,64),   256>>>(bias);
    k_out   <<<64, 128>>>(out);
}

// round 3
// speedup vs baseline: 1.0613x; 1.0613x over previous
#include <cuda_runtime.h>
#include <math.h>

#define BB 64
#define NN 512
#define DD 128
#define KT 32

typedef unsigned long long ull;

__device__ __forceinline__ ull pack2(float lo, float hi){
    ull r; asm("mov.b64 %0, {%1, %2};" : "=l"(r) : "f"(lo), "f"(hi)); return r;
}
__device__ __forceinline__ float2 unpack2(ull v){
    float2 f; asm("mov.b64 {%0, %1}, %2;" : "=f"(f.x), "=f"(f.y) : "l"(v)); return f;
}
__device__ __forceinline__ void fma2(ull &d, ull a, ull b){
    asm("fma.rn.f32x2 %0, %1, %2, %0;" : "+l"(d) : "l"(a), "l"(b));
}
__device__ __forceinline__ unsigned sm32(const void* p){
    return (unsigned)__cvta_generic_to_shared(p);
}
__device__ __forceinline__ void cp16(unsigned dst, const void* src){
    asm volatile("cp.async.cg.shared.global [%0], [%1], 16;" :: "r"(dst), "l"(src));
}
__device__ __forceinline__ void cp_commit(){ asm volatile("cp.async.commit_group;"); }
__device__ __forceinline__ void cp_wait0(){ asm volatile("cp.async.wait_group 0;" ::: "memory"); }

// Scratch (static device globals; no allocation)
__device__ float g_ET[BB*DD*NN];          // E transposed per batch: [b][d][i]
__device__ float g_z [BB*NN*DD];          // z = E @ W
__device__ float g_P [(size_t)BB*NN*NN];  // masked exp weights
__device__ float g_el[BB*NN];
__device__ float g_er[BB*NN];
__device__ float g_th[BB];
__device__ float g_cs[BB*4*NN];           // partial colsums per i-tile slot
__device__ float g_pool[BB*4*DD];         // partial pooled sums per j-tile

__constant__ int c_it[10] = {0,0,0,0,1,1,1,2,2,3};
__constant__ int c_jt[10] = {0,1,2,3,1,2,3,2,3,3};

// 32 FFMA2: row r broadcast (dup'd in regs), col pairs natural from LDS.128
#define FMA_BLOCK \
    { ull s; \
      s = pack2(a0.x,a0.x); fma2(acc[0][0],s,B0.x); fma2(acc[0][1],s,B0.y); fma2(acc[0][2],s,B1.x); fma2(acc[0][3],s,B1.y); \
      s = pack2(a0.y,a0.y); fma2(acc[1][0],s,B0.x); fma2(acc[1][1],s,B0.y); fma2(acc[1][2],s,B1.x); fma2(acc[1][3],s,B1.y); \
      s = pack2(a0.z,a0.z); fma2(acc[2][0],s,B0.x); fma2(acc[2][1],s,B0.y); fma2(acc[2][2],s,B1.x); fma2(acc[2][3],s,B1.y); \
      s = pack2(a0.w,a0.w); fma2(acc[3][0],s,B0.x); fma2(acc[3][1],s,B0.y); fma2(acc[3][2],s,B1.x); fma2(acc[3][3],s,B1.y); \
      s = pack2(a1.x,a1.x); fma2(acc[4][0],s,B0.x); fma2(acc[4][1],s,B0.y); fma2(acc[4][2],s,B1.x); fma2(acc[4][3],s,B1.y); \
      s = pack2(a1.y,a1.y); fma2(acc[5][0],s,B0.x); fma2(acc[5][1],s,B0.y); fma2(acc[5][2],s,B1.x); fma2(acc[5][3],s,B1.y); \
      s = pack2(a1.z,a1.z); fma2(acc[6][0],s,B0.x); fma2(acc[6][1],s,B0.y); fma2(acc[6][2],s,B1.x); fma2(acc[6][3],s,B1.y); \
      s = pack2(a1.w,a1.w); fma2(acc[7][0],s,B0.x); fma2(acc[7][1],s,B0.y); fma2(acc[7][2],s,B1.x); fma2(acc[7][3],s,B1.y); }

// Prefetch chunk k0 of A and B tiles into buf via cp.async (pure copies)
#define CPAB(bufidx, k0v, Abase, lda, Bbase, ldb) do { \
    int _k0 = (k0v); \
    _Pragma("unroll") \
    for (int _p = 0; _p < 4; _p++){ \
        int _f = tid + 256*_p; int _kk = _f >> 5; int _cc = (_f & 31) * 4; \
        cp16(sm32(&As[bufidx][_kk][_cc]), (Abase) + (size_t)(_k0+_kk)*(lda) + _cc); \
        cp16(sm32(&Bs[bufidx][_kk][_cc]), (Bbase) + (size_t)(_k0+_kk)*(ldb) + _cc); \
    } \
    cp_commit(); \
} while(0)

#define GEMM_CP(NC, Abase, lda, Bbase, ldb) \
    CPAB(0, 0, Abase, lda, Bbase, ldb); \
    cp_wait0(); \
    __syncthreads(); \
    _Pragma("unroll 1") \
    for (int c = 0; c < (NC); c++){ \
        int buf = c & 1; \
        if (c + 1 < (NC)) CPAB(buf^1, (c+1)*KT, Abase, lda, Bbase, ldb); \
        _Pragma("unroll") \
        for (int k = 0; k < KT; k++){ \
            float4 a0 = *(const float4*)&As[buf][k][ty*4]; \
            float4 a1 = *(const float4*)&As[buf][k][64 + ty*4]; \
            ulonglong2 B0 = *(const ulonglong2*)&Bs[buf][k][4*tx]; \
            ulonglong2 B1 = *(const ulonglong2*)&Bs[buf][k][64 + 4*tx]; \
            FMA_BLOCK \
        } \
        if (c + 1 < (NC)){ cp_wait0(); __syncthreads(); } \
    }

// ---------------- transpose: g_ET[b][d][i] = E[b][i][d] ----------------
__global__ void k_T(const float* __restrict__ E){
    __shared__ float t[32][33];
    int b  = blockIdx.z;
    int i0 = blockIdx.x * 32;
    int d0 = blockIdx.y * 32;
    int tx = threadIdx.x, ty = threadIdx.y;   // (32, 8)
    const float* Eb = E + (size_t)b*NN*DD;
    #pragma unroll
    for (int yy = 0; yy < 32; yy += 8)
        t[ty+yy][tx] = Eb[(size_t)(i0+ty+yy)*DD + d0 + tx];
    __syncthreads();
    float* ETb = g_ET + (size_t)b*DD*NN;
    #pragma unroll
    for (int yy = 0; yy < 32; yy += 8)
        ETb[(size_t)(d0+ty+yy)*NN + i0 + tx] = t[tx][ty+yy];
}

// ---------------- thresh[b] = ||sum_i e_i||^2 / N^2 ----------------
__global__ void k_thresh(const float* __restrict__ E){
    int b = blockIdx.x; int t = threadIdx.x;  // 128 threads
    const float* Eb = E + (size_t)b*NN*DD;
    float s = 0.f;
    for (int i = 0; i < NN; i++) s += Eb[(size_t)i*DD + t];
    __shared__ float red[DD];
    red[t] = s * s;
    __syncthreads();
    for (int o = 64; o > 0; o >>= 1){
        if (t < o) red[t] += red[t+o];
        __syncthreads();
    }
    if (t == 0) g_th[b] = red[0] * (1.f / ((float)NN * (float)NN));
}

// ---------------- z = E @ W  (+ fused el/er) ----------------
__global__ void __launch_bounds__(256,2) k_z(const float* __restrict__ W,
                                             const float* __restrict__ attn_l,
                                             const float* __restrict__ attn_r){
    __shared__ float As[2][KT][128];
    __shared__ float Bs[2][KT][128];
    int it = blockIdx.x, b = blockIdx.y;
    int tid = threadIdx.x, tx = tid & 15, ty = tid >> 4;
    const float* ETb = g_ET + (size_t)b*DD*NN;
    int i0 = it * 128;
    const float* Abase = ETb + i0;

    ull acc[8][4];
    #pragma unroll
    for (int r = 0; r < 8; r++)
        #pragma unroll
        for (int p = 0; p < 4; p++) acc[r][p] = 0ull;

    GEMM_CP(DD/KT, Abase, NN, W, DD)

    float al[8], ar[8];
    #pragma unroll
    for (int s = 0; s < 8; s++){
        int d = tx*4 + (s&3) + ((s>>2)<<6);
        al[s] = attn_l[d]; ar[s] = attn_r[d];
    }
    float elp[8], erp[8];
    float* zb = g_z + (size_t)b*NN*DD;
    #pragma unroll
    for (int r = 0; r < 8; r++){
        int i = i0 + ty*4 + (r&3) + ((r>>2)<<6);
        float v[8];
        #pragma unroll
        for (int p = 0; p < 4; p++){ float2 u = unpack2(acc[r][p]); v[p*2] = u.x; v[p*2+1] = u.y; }
        *(float4*)&zb[(size_t)i*DD + tx*4]      = make_float4(v[0],v[1],v[2],v[3]);
        *(float4*)&zb[(size_t)i*DD + 64 + tx*4] = make_float4(v[4],v[5],v[6],v[7]);
        float pe = 0.f, pr = 0.f;
        #pragma unroll
        for (int s = 0; s < 8; s++){ pe += v[s]*al[s]; pr += v[s]*ar[s]; }
        elp[r] = pe; erp[r] = pr;
    }
    __syncthreads();
    float* redl = &As[0][0][0];
    float* redr = redl + 2048;
    #pragma unroll
    for (int r = 0; r < 8; r++){
        int il = ty*4 + (r&3) + ((r>>2)<<6);
        redl[tx*128 + il] = elp[r];
        redr[tx*128 + il] = erp[r];
    }
    __syncthreads();
    if (tid < 128){
        float se = 0.f, sr = 0.f;
        #pragma unroll
        for (int x = 0; x < 16; x++){ se += redl[x*128 + tid]; sr += redr[x*128 + tid]; }
        g_el[b*NN + i0 + tid] = se;
        g_er[b*NN + i0 + tid] = sr;
    }
}

// ---------------- scores (triangular) -> P both blocks, colsum partials ----------------
__global__ void __launch_bounds__(256,2) k_scoresS(){
    __shared__ float As[2][KT][128];
    __shared__ float Bs[2][KT][128];
    int pr_ = blockIdx.x, b = blockIdx.z ? 0 : blockIdx.y;  // grid (10, 64)
    b = blockIdx.y;
    int it = c_it[pr_], jt = c_jt[pr_];
    int tid = threadIdx.x, tx = tid & 15, ty = tid >> 4;
    const float* ETb = g_ET + (size_t)b*DD*NN;
    int i0 = it * 128, j0 = jt * 128;
    const float* Abase = ETb + i0;
    const float* Bbase = ETb + j0;

    ull acc[8][4];
    #pragma unroll
    for (int r = 0; r < 8; r++)
        #pragma unroll
        for (int p = 0; p < 4; p++) acc[r][p] = 0ull;

    GEMM_CP(DD/KT, Abase, NN, Bbase, NN)

    float th = g_th[b];
    int gi[8], gj[8]; float eli[8], erj[8], elj[8], eri[8];
    #pragma unroll
    for (int r = 0; r < 8; r++){
        gi[r] = i0 + ty*4 + (r&3) + ((r>>2)<<6);
        eli[r] = g_el[b*NN + gi[r]]; eri[r] = g_er[b*NN + gi[r]];
    }
    #pragma unroll
    for (int s = 0; s < 8; s++){
        gj[s] = j0 + tx*4 + (s&3) + ((s>>2)<<6);
        erj[s] = g_er[b*NN + gj[s]]; elj[s] = g_el[b*NN + gj[s]];
    }

    // ---- primary block P[i][j] + colsum over i (slot it, colblock jt)
    float cs[8];
    #pragma unroll
    for (int s = 0; s < 8; s++) cs[s] = 0.f;
    float* Pb = g_P + (size_t)b*NN*NN;
    #pragma unroll
    for (int r = 0; r < 8; r++){
        float v[8];
        #pragma unroll
        for (int p = 0; p < 4; p++){ float2 u = unpack2(acc[r][p]); v[p*2] = u.x; v[p*2+1] = u.y; }
        float pv[8];
        #pragma unroll
        for (int s = 0; s < 8; s++){
            float e = eli[r] + erj[s];
            e = e > 0.f ? e : 0.2f * e;
            float p = (v[s] > th || gi[r] == gj[s]) ? __expf(e) : 0.f;
            pv[s] = p; cs[s] += p;
        }
        *(float4*)&Pb[(size_t)gi[r]*NN + j0 + tx*4]      = make_float4(pv[0],pv[1],pv[2],pv[3]);
        *(float4*)&Pb[(size_t)gi[r]*NN + j0 + 64 + tx*4] = make_float4(pv[4],pv[5],pv[6],pv[7]);
    }
    float* red = &Bs[0][0][0];        // [0,2048)
    #pragma unroll
    for (int s = 0; s < 8; s++) red[ty*128 + (gj[s]-j0)] = cs[s];
    __syncthreads();
    if (tid < 128){
        float t = 0.f;
        #pragma unroll
        for (int x = 0; x < 16; x++) t += red[x*128 + tid];
        g_cs[(b*4 + it)*NN + j0 + tid] = t;
    }

    if (it == jt) return;

    // ---- mirrored block P[j][i] via smem transpose (reuse As region), colsum slot jt/colblock it
    float (*Ts)[132] = (float(*)[132])&As[0][0][0];   // 32 x 132 floats = 16.5KB <= 32KB
    float cs2[8];
    #pragma unroll
    for (int r = 0; r < 8; r++) cs2[r] = 0.f;

    #pragma unroll 1
    for (int c4 = 0; c4 < 4; c4++){
        bool part = ((tx >> 3) == (c4 & 1));
        int sbase = (c4 >> 1) * 4;
        if (part){
            #pragma unroll
            for (int ss = 0; ss < 4; ss++){
                int s = sbase + ss;
                int j_loc = 4*(tx & 7) + ss;
                float tvals[8];
                #pragma unroll
                for (int r = 0; r < 8; r++){
                    float2 u = unpack2(acc[r][s>>1]);
                    float vrs = (s & 1) ? u.y : u.x;
                    float e = elj[s] + eri[r];
                    e = e > 0.f ? e : 0.2f * e;
                    float p = (vrs > th || gi[r] == gj[s]) ? __expf(e) : 0.f;
                    tvals[r] = p; cs2[r] += p;
                }
                *(float4*)&Ts[j_loc][ty*4]      = make_float4(tvals[0],tvals[1],tvals[2],tvals[3]);
                *(float4*)&Ts[j_loc][64 + ty*4] = make_float4(tvals[4],tvals[5],tvals[6],tvals[7]);
            }
        }
        __syncthreads();
        int jr = tid >> 3, c0 = (tid & 7) * 16;
        size_t rowbase = (size_t)(j0 + 32*c4 + jr)*NN + i0;
        #pragma unroll
        for (int q = 0; q < 4; q++)
            *(float4*)&Pb[rowbase + c0 + 4*q] = *(float4*)&Ts[jr][c0 + 4*q];
        __syncthreads();
    }
    float* red2 = &Bs[0][0][0] + 2048;   // [2048,4096)
    #pragma unroll
    for (int r = 0; r < 8; r++) red2[tx*128 + (gi[r]-i0)] = cs2[r];
    __syncthreads();
    if (tid < 128){
        float t = 0.f;
        #pragma unroll
        for (int x = 0; x < 16; x++) t += red2[x*128 + tid];
        g_cs[(b*4 + jt)*NN + i0 + tid] = t;
    }
}

// ---------------- h = P^T z / colsum; elu(+bias); partial pool ----------------
__global__ void __launch_bounds__(256,2) k_pv(const float* __restrict__ bias){
    __shared__ float As[2][KT][128];
    __shared__ float Bs[2][KT][128];
    int jt = blockIdx.x, b = blockIdx.y;
    int tid = threadIdx.x, tx = tid & 15, ty = tid >> 4;
    const float* Pb = g_P + (size_t)b*NN*NN;
    const float* zb = g_z + (size_t)b*NN*DD;
    int j0 = jt * 128;
    const float* Abase = Pb + j0;   // A[k=i][m=j]

    ull acc[8][4];
    #pragma unroll
    for (int r = 0; r < 8; r++)
        #pragma unroll
        for (int p = 0; p < 4; p++) acc[r][p] = 0ull;

    GEMM_CP(NN/KT, Abase, NN, zb, DD)

    float inv[8];
    #pragma unroll
    for (int r = 0; r < 8; r++){
        int j = j0 + ty*4 + (r&3) + ((r>>2)<<6);
        float c0 = g_cs[(b*4 + 0)*NN + j] + g_cs[(b*4 + 1)*NN + j]
                 + g_cs[(b*4 + 2)*NN + j] + g_cs[(b*4 + 3)*NN + j];
        inv[r] = 1.f / c0;
    }
    float bi[8]; int dl[8];
    #pragma unroll
    for (int s = 0; s < 8; s++){ dl[s] = tx*4 + (s&3) + ((s>>2)<<6); bi[s] = bias[dl[s]]; }

    float pd[8];
    #pragma unroll
    for (int s = 0; s < 8; s++) pd[s] = 0.f;
    #pragma unroll
    for (int r = 0; r < 8; r++){
        float v[8];
        #pragma unroll
        for (int p = 0; p < 4; p++){ float2 u = unpack2(acc[r][p]); v[p*2] = u.x; v[p*2+1] = u.y; }
        #pragma unroll
        for (int s = 0; s < 8; s++){
            float h = v[s]*inv[r] + bi[s];
            h = h > 0.f ? h : expm1f(h);
            pd[s] += h;
        }
    }
    __syncthreads();
    float* red = &As[0][0][0];
    #pragma unroll
    for (int s = 0; s < 8; s++) red[ty*128 + dl[s]] = pd[s];
    __syncthreads();
    if (tid < 128){
        float t = 0.f;
        #pragma unroll
        for (int x = 0; x < 16; x++) t += red[x*128 + tid];
        g_pool[(b*4 + jt)*DD + tid] = t;
    }
}

// ---------------- final: mean over nodes ----------------
__global__ void k_out(float* __restrict__ out){
    int b = blockIdx.x, d = threadIdx.x;
    float s = g_pool[(b*4+0)*DD + d] + g_pool[(b*4+1)*DD + d]
            + g_pool[(b*4+2)*DD + d] + g_pool[(b*4+3)*DD + d];
    out[b*DD + d] = s * (1.f / (float)NN);
}

extern "C" void kernel_launch(void* const* d_in, const int* in_sizes, int n_in,
                              void* d_out, int out_size){
    const float* E    = (const float*)d_in[0];
    const float* W    = (const float*)d_in[1];
    const float* al   = (const float*)d_in[2];
    const float* ar   = (const float*)d_in[3];
    const float* bias = (const float*)d_in[4];
    float* out = (float*)d_out;

    k_T      <<<dim3(16,4,64), dim3(32,8)>>>(E);
    k_thresh <<<64, 128>>>(E);
    k_z      <<<dim3(4,64),   256>>>(W, al, ar);
    k_scoresS<<<dim3(10,64),  256>>>();
    k_pv     <<<dim3(4,64),   256>>>(bias);
    k_out    <<<64, 128>>>(out);
}

// round 4
// speedup vs baseline: 1.2033x; 1.1338x over previous
#include <cuda_runtime.h>
#include <math.h>

#define BB 64
#define NN 512
#define DD 128
#define KT 16

typedef unsigned long long ull;

__device__ __forceinline__ ull pack2(float lo, float hi){
    ull r; asm("mov.b64 %0, {%1, %2};" : "=l"(r) : "f"(lo), "f"(hi)); return r;
}
__device__ __forceinline__ float2 unpack2(ull v){
    float2 f; asm("mov.b64 {%0, %1}, %2;" : "=f"(f.x), "=f"(f.y) : "l"(v)); return f;
}
__device__ __forceinline__ void fma2(ull &d, ull a, ull b){
    asm("fma.rn.f32x2 %0, %1, %2, %0;" : "+l"(d) : "l"(a), "l"(b));
}
__device__ __forceinline__ unsigned sm32(const void* p){
    return (unsigned)__cvta_generic_to_shared(p);
}
__device__ __forceinline__ void cp16(unsigned dst, const void* src){
    asm volatile("cp.async.cg.shared.global [%0], [%1], 16;" :: "r"(dst), "l"(src));
}
__device__ __forceinline__ void cp_commit(){ asm volatile("cp.async.commit_group;"); }
__device__ __forceinline__ void cp_wait0(){ asm volatile("cp.async.wait_group 0;" ::: "memory"); }

// Scratch (static device globals; no allocation)
__device__ float g_ET[BB*DD*NN];          // E transposed per batch: [b][d][i]
__device__ float g_z [BB*NN*DD];          // z = E @ W
__device__ float g_P [(size_t)BB*NN*NN];  // masked exp weights
__device__ float g_el[BB*NN];
__device__ float g_er[BB*NN];
__device__ float g_th[BB];
__device__ float g_cs[BB*4*NN];           // partial colsums per slot
__device__ float g_pool[BB*4*DD];         // partial pooled sums per j-tile

__constant__ int c_it[10] = {0,0,0,0,1,1,1,2,2,3};
__constant__ int c_jt[10] = {0,1,2,3,1,2,3,2,3,3};

// 32 FFMA2: row r broadcast, col pairs natural from LDS.128
#define FMA_BLOCK \
    { ull s; \
      s = pack2(a0.x,a0.x); fma2(acc[0][0],s,B0.x); fma2(acc[0][1],s,B0.y); fma2(acc[0][2],s,B1.x); fma2(acc[0][3],s,B1.y); \
      s = pack2(a0.y,a0.y); fma2(acc[1][0],s,B0.x); fma2(acc[1][1],s,B0.y); fma2(acc[1][2],s,B1.x); fma2(acc[1][3],s,B1.y); \
      s = pack2(a0.z,a0.z); fma2(acc[2][0],s,B0.x); fma2(acc[2][1],s,B0.y); fma2(acc[2][2],s,B1.x); fma2(acc[2][3],s,B1.y); \
      s = pack2(a0.w,a0.w); fma2(acc[3][0],s,B0.x); fma2(acc[3][1],s,B0.y); fma2(acc[3][2],s,B1.x); fma2(acc[3][3],s,B1.y); \
      s = pack2(a1.x,a1.x); fma2(acc[4][0],s,B0.x); fma2(acc[4][1],s,B0.y); fma2(acc[4][2],s,B1.x); fma2(acc[4][3],s,B1.y); \
      s = pack2(a1.y,a1.y); fma2(acc[5][0],s,B0.x); fma2(acc[5][1],s,B0.y); fma2(acc[5][2],s,B1.x); fma2(acc[5][3],s,B1.y); \
      s = pack2(a1.z,a1.z); fma2(acc[6][0],s,B0.x); fma2(acc[6][1],s,B0.y); fma2(acc[6][2],s,B1.x); fma2(acc[6][3],s,B1.y); \
      s = pack2(a1.w,a1.w); fma2(acc[7][0],s,B0.x); fma2(acc[7][1],s,B0.y); fma2(acc[7][2],s,B1.x); fma2(acc[7][3],s,B1.y); }

// Prefetch chunk k0 of A and B tiles into buf via cp.async (pure copies, KT=16)
#define CPAB(bufidx, k0v, Abase, lda, Bbase, ldb) do { \
    int _k0 = (k0v); \
    _Pragma("unroll") \
    for (int _p = 0; _p < 2; _p++){ \
        int _f = tid + 256*_p; int _kk = _f >> 5; int _cc = (_f & 31) * 4; \
        cp16(sm32(&As[bufidx][_kk][_cc]), (Abase) + (size_t)(_k0+_kk)*(lda) + _cc); \
        cp16(sm32(&Bs[bufidx][_kk][_cc]), (Bbase) + (size_t)(_k0+_kk)*(ldb) + _cc); \
    } \
    cp_commit(); \
} while(0)

#define GEMM_CP(NC, Abase, lda, Bbase, ldb) \
    CPAB(0, 0, Abase, lda, Bbase, ldb); \
    cp_wait0(); \
    __syncthreads(); \
    _Pragma("unroll 1") \
    for (int c = 0; c < (NC); c++){ \
        int buf = c & 1; \
        if (c + 1 < (NC)) CPAB(buf^1, (c+1)*KT, Abase, lda, Bbase, ldb); \
        _Pragma("unroll") \
        for (int k = 0; k < KT; k++){ \
            float4 a0 = *(const float4*)&As[buf][k][ty*4]; \
            float4 a1 = *(const float4*)&As[buf][k][64 + ty*4]; \
            ulonglong2 B0 = *(const ulonglong2*)&Bs[buf][k][4*tx]; \
            ulonglong2 B1 = *(const ulonglong2*)&Bs[buf][k][64 + 4*tx]; \
            FMA_BLOCK \
        } \
        if (c + 1 < (NC)){ cp_wait0(); __syncthreads(); } \
    }

// ---------------- transpose: g_ET[b][d][i] = E[b][i][d] ----------------
__global__ void k_T(const float* __restrict__ E){
    __shared__ float t[32][33];
    int b  = blockIdx.z;
    int i0 = blockIdx.x * 32;
    int d0 = blockIdx.y * 32;
    int tx = threadIdx.x, ty = threadIdx.y;   // (32, 8)
    const float* Eb = E + (size_t)b*NN*DD;
    #pragma unroll
    for (int yy = 0; yy < 32; yy += 8)
        t[ty+yy][tx] = Eb[(size_t)(i0+ty+yy)*DD + d0 + tx];
    __syncthreads();
    float* ETb = g_ET + (size_t)b*DD*NN;
    #pragma unroll
    for (int yy = 0; yy < 32; yy += 8)
        ETb[(size_t)(d0+ty+yy)*NN + i0 + tx] = t[tx][ty+yy];
}

// ---------------- thresh[b] = ||sum_i e_i||^2 / N^2 ----------------
__global__ void k_thresh(const float* __restrict__ E){
    int b = blockIdx.x; int t = threadIdx.x;  // 128 threads
    const float* Eb = E + (size_t)b*NN*DD;
    float s = 0.f;
    for (int i = 0; i < NN; i++) s += Eb[(size_t)i*DD + t];
    __shared__ float red[DD];
    red[t] = s * s;
    __syncthreads();
    for (int o = 64; o > 0; o >>= 1){
        if (t < o) red[t] += red[t+o];
        __syncthreads();
    }
    if (t == 0) g_th[b] = red[0] * (1.f / ((float)NN * (float)NN));
}

// ---------------- z = E @ W  (+ fused el/er) ----------------
__global__ void __launch_bounds__(256,2) k_z(const float* __restrict__ W,
                                             const float* __restrict__ attn_l,
                                             const float* __restrict__ attn_r){
    __shared__ float As[2][KT][128];
    __shared__ float Bs[2][KT][128];
    int it = blockIdx.x, b = blockIdx.y;
    int tid = threadIdx.x, tx = tid & 15, ty = tid >> 4;
    const float* ETb = g_ET + (size_t)b*DD*NN;
    int i0 = it * 128;
    const float* Abase = ETb + i0;

    ull acc[8][4];
    #pragma unroll
    for (int r = 0; r < 8; r++)
        #pragma unroll
        for (int p = 0; p < 4; p++) acc[r][p] = 0ull;

    GEMM_CP(DD/KT, Abase, NN, W, DD)

    float al[8], ar[8];
    #pragma unroll
    for (int s = 0; s < 8; s++){
        int d = tx*4 + (s&3) + ((s>>2)<<6);
        al[s] = attn_l[d]; ar[s] = attn_r[d];
    }
    float elp[8], erp[8];
    float* zb = g_z + (size_t)b*NN*DD;
    #pragma unroll
    for (int r = 0; r < 8; r++){
        int i = i0 + ty*4 + (r&3) + ((r>>2)<<6);
        float v[8];
        #pragma unroll
        for (int p = 0; p < 4; p++){ float2 u = unpack2(acc[r][p]); v[p*2] = u.x; v[p*2+1] = u.y; }
        *(float4*)&zb[(size_t)i*DD + tx*4]      = make_float4(v[0],v[1],v[2],v[3]);
        *(float4*)&zb[(size_t)i*DD + 64 + tx*4] = make_float4(v[4],v[5],v[6],v[7]);
        float pe = 0.f, pr = 0.f;
        #pragma unroll
        for (int s = 0; s < 8; s++){ pe += v[s]*al[s]; pr += v[s]*ar[s]; }
        elp[r] = pe; erp[r] = pr;
    }
    __syncthreads();
    float* redl = &As[0][0][0];
    float* redr = redl + 2048;
    #pragma unroll
    for (int r = 0; r < 8; r++){
        int il = ty*4 + (r&3) + ((r>>2)<<6);
        redl[tx*128 + il] = elp[r];
        redr[tx*128 + il] = erp[r];
    }
    __syncthreads();
    if (tid < 128){
        float se = 0.f, sr = 0.f;
        #pragma unroll
        for (int x = 0; x < 16; x++){ se += redl[x*128 + tid]; sr += redr[x*128 + tid]; }
        g_el[b*NN + i0 + tid] = se;
        g_er[b*NN + i0 + tid] = sr;
    }
}

// ---------------- scores (triangular) -> P both blocks, colsum partials ----------------
__global__ void __launch_bounds__(256,2) k_scoresS(){
    __shared__ float As[2][KT][128];
    __shared__ float Bs[2][KT][128];
    int pr_ = blockIdx.x, b = blockIdx.y;  // grid (10, 64)
    int it = c_it[pr_], jt = c_jt[pr_];
    int tid = threadIdx.x, tx = tid & 15, ty = tid >> 4;
    const float* ETb = g_ET + (size_t)b*DD*NN;
    int i0 = it * 128, j0 = jt * 128;
    const float* Abase = ETb + i0;
    const float* Bbase = ETb + j0;

    ull acc[8][4];
    #pragma unroll
    for (int r = 0; r < 8; r++)
        #pragma unroll
        for (int p = 0; p < 4; p++) acc[r][p] = 0ull;

    GEMM_CP(DD/KT, Abase, NN, Bbase, NN)

    float th = g_th[b];
    int gi[8], gj[8]; float eli[8], erj[8], elj[8], eri[8];
    #pragma unroll
    for (int r = 0; r < 8; r++){
        gi[r] = i0 + ty*4 + (r&3) + ((r>>2)<<6);
        eli[r] = g_el[b*NN + gi[r]]; eri[r] = g_er[b*NN + gi[r]];
    }
    #pragma unroll
    for (int s = 0; s < 8; s++){
        gj[s] = j0 + tx*4 + (s&3) + ((s>>2)<<6);
        erj[s] = g_er[b*NN + gj[s]]; elj[s] = g_el[b*NN + gj[s]];
    }

    // ---- primary block P[i][j] from registers; colsum over i (slot it, colblock jt)
    float cs[8];
    #pragma unroll
    for (int s = 0; s < 8; s++) cs[s] = 0.f;
    float* Pb = g_P + (size_t)b*NN*NN;
    #pragma unroll
    for (int r = 0; r < 8; r++){
        float v[8];
        #pragma unroll
        for (int p = 0; p < 4; p++){ float2 u = unpack2(acc[r][p]); v[p*2] = u.x; v[p*2+1] = u.y; }
        float pv[8];
        #pragma unroll
        for (int s = 0; s < 8; s++){
            float e = eli[r] + erj[s];
            e = e > 0.f ? e : 0.2f * e;
            float p = (v[s] > th || gi[r] == gj[s]) ? __expf(e) : 0.f;
            pv[s] = p; cs[s] += p;
        }
        *(float4*)&Pb[(size_t)gi[r]*NN + j0 + tx*4]      = make_float4(pv[0],pv[1],pv[2],pv[3]);
        *(float4*)&Pb[(size_t)gi[r]*NN + j0 + 64 + tx*4] = make_float4(pv[4],pv[5],pv[6],pv[7]);
    }
    float* red = &Bs[0][0][0];        // Bs[0] region: safe (last chunk read Bs[1])
    #pragma unroll
    for (int s = 0; s < 8; s++) red[ty*128 + (gj[s]-j0)] = cs[s];
    __syncthreads();
    if (tid < 128){
        float t = 0.f;
        #pragma unroll
        for (int x = 0; x < 16; x++) t += red[x*128 + tid];
        g_cs[(b*4 + it)*NN + j0 + tid] = t;
    }

    if (it == jt) return;

    // ---- mirrored block P[j][i] written straight from registers (no smem transpose)
    float cs2[8];
    #pragma unroll
    for (int r = 0; r < 8; r++) cs2[r] = 0.f;
    #pragma unroll
    for (int s = 0; s < 8; s++){
        float tv[8];
        #pragma unroll
        for (int r = 0; r < 8; r++){
            float2 u = unpack2(acc[r][s>>1]);
            float vrs = (s & 1) ? u.y : u.x;
            float e = elj[s] + eri[r];
            e = e > 0.f ? e : 0.2f * e;
            float p = (vrs > th || gi[r] == gj[s]) ? __expf(e) : 0.f;
            tv[r] = p; cs2[r] += p;
        }
        size_t rowb = (size_t)gj[s]*NN + i0;
        *(float4*)&Pb[rowb + ty*4]      = make_float4(tv[0],tv[1],tv[2],tv[3]);
        *(float4*)&Pb[rowb + 64 + ty*4] = make_float4(tv[4],tv[5],tv[6],tv[7]);
    }
    float* red2 = &Bs[0][0][0] + 2048;   // Bs[1] region: all GEMM reads done (post-sync)
    #pragma unroll
    for (int r = 0; r < 8; r++) red2[tx*128 + (gi[r]-i0)] = cs2[r];
    __syncthreads();
    if (tid < 128){
        float t = 0.f;
        #pragma unroll
        for (int x = 0; x < 16; x++) t += red2[x*128 + tid];
        g_cs[(b*4 + jt)*NN + i0 + tid] = t;
    }
}

// ---------------- h = P^T z / colsum; elu(+bias); partial pool ----------------
__global__ void __launch_bounds__(256,2) k_pv(const float* __restrict__ bias){
    __shared__ float As[2][KT][128];
    __shared__ float Bs[2][KT][128];
    int jt = blockIdx.x, b = blockIdx.y;
    int tid = threadIdx.x, tx = tid & 15, ty = tid >> 4;
    const float* Pb = g_P + (size_t)b*NN*NN;
    const float* zb = g_z + (size_t)b*NN*DD;
    int j0 = jt * 128;
    const float* Abase = Pb + j0;   // A[k=i][m=j]

    ull acc[8][4];
    #pragma unroll
    for (int r = 0; r < 8; r++)
        #pragma unroll
        for (int p = 0; p < 4; p++) acc[r][p] = 0ull;

    GEMM_CP(NN/KT, Abase, NN, zb, DD)

    float inv[8];
    #pragma unroll
    for (int r = 0; r < 8; r++){
        int j = j0 + ty*4 + (r&3) + ((r>>2)<<6);
        float c0 = g_cs[(b*4 + 0)*NN + j] + g_cs[(b*4 + 1)*NN + j]
                 + g_cs[(b*4 + 2)*NN + j] + g_cs[(b*4 + 3)*NN + j];
        inv[r] = 1.f / c0;
    }
    float bi[8]; int dl[8];
    #pragma unroll
    for (int s = 0; s < 8; s++){ dl[s] = tx*4 + (s&3) + ((s>>2)<<6); bi[s] = bias[dl[s]]; }

    float pd[8];
    #pragma unroll
    for (int s = 0; s < 8; s++) pd[s] = 0.f;
    #pragma unroll
    for (int r = 0; r < 8; r++){
        float v[8];
        #pragma unroll
        for (int p = 0; p < 4; p++){ float2 u = unpack2(acc[r][p]); v[p*2] = u.x; v[p*2+1] = u.y; }
        #pragma unroll
        for (int s = 0; s < 8; s++){
            float h = v[s]*inv[r] + bi[s];
            h = h > 0.f ? h : expm1f(h);
            pd[s] += h;
        }
    }
    __syncthreads();
    float* red = &As[0][0][0];
    #pragma unroll
    for (int s = 0; s < 8; s++) red[ty*128 + dl[s]] = pd[s];
    __syncthreads();
    if (tid < 128){
        float t = 0.f;
        #pragma unroll
        for (int x = 0; x < 16; x++) t += red[x*128 + tid];
        g_pool[(b*4 + jt)*DD + tid] = t;
    }
}

// ---------------- final: mean over nodes ----------------
__global__ void k_out(float* __restrict__ out){
    int b = blockIdx.x, d = threadIdx.x;
    float s = g_pool[(b*4+0)*DD + d] + g_pool[(b*4+1)*DD + d]
            + g_pool[(b*4+2)*DD + d] + g_pool[(b*4+3)*DD + d];
    out[b*DD + d] = s * (1.f / (float)NN);
}

extern "C" void kernel_launch(void* const* d_in, const int* in_sizes, int n_in,
                              void* d_out, int out_size){
    const float* E    = (const float*)d_in[0];
    const float* W    = (const float*)d_in[1];
    const float* al   = (const float*)d_in[2];
    const float* ar   = (const float*)d_in[3];
    const float* bias = (const float*)d_in[4];
    float* out = (float*)d_out;

    k_T      <<<dim3(16,4,64), dim3(32,8)>>>(E);
    k_thresh <<<64, 128>>>(E);
    k_z      <<<dim3(4,64),   256>>>(W, al, ar);
    k_scoresS<<<dim3(10,64),  256>>>();
    k_pv     <<<dim3(4,64),   256>>>(bias);
    k_out    <<<64, 128>>>(out);
}